// round 7
// baseline (speedup 1.0000x reference)
#include <cuda_runtime.h>
#include <cuda_bf16.h>
#include <math.h>
#include <stdint.h>

#define BDIM 4096
#define DDIM 512
#define NBINS 10
#define TILE 128
#define NT   32            // tiles per dimension
#define NTRI 528           // NT*(NT+1)/2 upper-triangular tiles
#define KC   16            // bf16 K-elements per pipeline stage (32 B/row)
#define NST  (DDIM / KC)   // 32 stages
#define SROWB 48           // padded SMEM row stride bytes (32B data + 16B pad)
#define TILE_SMEMB (TILE * SROWB)     // 6144 B per tile
#define STAGE_B (4 * TILE_SMEMB)      // A_hi, A_lo, B_hi, B_lo = 24576 B
#define NSTAGE 4
#define DYN_SMEM (NSTAGE * STAGE_B)   // 98304 B

// ---------------------------------------------------------------------------
// device scratch (no allocations allowed)
// ---------------------------------------------------------------------------
__device__ __nv_bfloat16 g_hi[BDIM * DDIM];
__device__ __nv_bfloat16 g_lo[BDIM * DDIM];
__device__ int   g_tgt[BDIM];
__device__ float g_cntf[NBINS];
__device__ float g_sum[NBINS];
__device__ int   g_ticket;

// ---------------------------------------------------------------------------
// helpers (base-ISA only: cp.async, ldmatrix, mma.sync — all compute_103-safe)
// ---------------------------------------------------------------------------
__device__ __forceinline__ uint32_t smem_to_u32(const void* p) {
    uint32_t a;
    asm("{ .reg .u64 t; cvta.to.shared.u64 t, %1; cvt.u32.u64 %0, t; }"
        : "=r"(a) : "l"(p));
    return a;
}
__device__ __forceinline__ void cp16(uint32_t dst, const void* src) {
    asm volatile("cp.async.cg.shared.global [%0], [%1], 16;" :: "r"(dst), "l"(src));
}
#define CP_COMMIT() asm volatile("cp.async.commit_group;" ::: "memory")
#define CP_WAIT(n)  asm volatile("cp.async.wait_group %0;" :: "n"(n) : "memory")

__device__ __forceinline__ void ldsm_x4(uint32_t* r, uint32_t addr) {
    asm volatile("ldmatrix.sync.aligned.m8n8.x4.shared.b16 {%0,%1,%2,%3}, [%4];"
                 : "=r"(r[0]), "=r"(r[1]), "=r"(r[2]), "=r"(r[3]) : "r"(addr));
}
__device__ __forceinline__ void ldsm_x2(uint32_t* r, uint32_t addr) {
    asm volatile("ldmatrix.sync.aligned.m8n8.x2.shared.b16 {%0,%1}, [%2];"
                 : "=r"(r[0]), "=r"(r[1]) : "r"(addr));
}
__device__ __forceinline__ void mma_bf16(float* d, const uint32_t* a, const uint32_t* b) {
    asm volatile("mma.sync.aligned.m16n8k16.row.col.f32.bf16.bf16.f32 "
                 "{%0,%1,%2,%3}, {%4,%5,%6,%7}, {%8,%9}, {%0,%1,%2,%3};"
                 : "+f"(d[0]), "+f"(d[1]), "+f"(d[2]), "+f"(d[3])
                 : "r"(a[0]), "r"(a[1]), "r"(a[2]), "r"(a[3]),
                   "r"(b[0]), "r"(b[1]));
}

// ---------------------------------------------------------------------------
// Kernel 1: blocks 0..4095 normalize+split rows; block 4096 decodes targets
// (sniffs int32 vs int64 storage) and zeros the histogram/ticket state.
// ---------------------------------------------------------------------------
__global__ void prep_kernel(const float* __restrict__ x,
                            const int* __restrict__ tgt_words) {
    int blk = blockIdx.x;
    int tid = threadIdx.x;  // 0..127

    if (blk == BDIM) {
        __shared__ int s_any_odd;
        if (tid == 0) s_any_odd = 0;
        __syncthreads();
        int local = 0;
        #pragma unroll
        for (int r = 0; r < 32; r++) {
            int i = tid + r * 128;
            local |= tgt_words[2 * i + 1];   // odd word under int64 hypothesis
        }
        if (local) atomicOr(&s_any_odd, 1);
        __syncthreads();
        bool is32 = (s_any_odd != 0);
        #pragma unroll
        for (int r = 0; r < 32; r++) {
            int i = tid + r * 128;
            g_tgt[i] = is32 ? tgt_words[i] : tgt_words[2 * i];
        }
        if (tid < NBINS) { g_cntf[tid] = 0.0f; g_sum[tid] = 0.0f; }
        if (tid == 0) g_ticket = 0;
        return;
    }

    float4 v = ((const float4*)(x + (size_t)blk * DDIM))[tid];
    float ss = v.x * v.x + v.y * v.y + v.z * v.z + v.w * v.w;
    #pragma unroll
    for (int o = 16; o > 0; o >>= 1) ss += __shfl_down_sync(0xffffffffu, ss, o);
    __shared__ float ws[4];
    if ((tid & 31) == 0) ws[tid >> 5] = ss;
    __syncthreads();
    float tot = ws[0] + ws[1] + ws[2] + ws[3];
    float inv = 1.0f / fmaxf(sqrtf(tot), 1e-12f);

    float f[4] = {v.x * inv, v.y * inv, v.z * inv, v.w * inv};
    __nv_bfloat16 h[4], l[4];
    #pragma unroll
    for (int i = 0; i < 4; i++) {
        h[i] = __float2bfloat16(f[i]);
        l[i] = __float2bfloat16(f[i] - __bfloat162float(h[i]));
    }
    size_t base = (size_t)blk * DDIM + tid * 4;
    *(__nv_bfloat162*)(g_hi + base)     = __nv_bfloat162(h[0], h[1]);
    *(__nv_bfloat162*)(g_hi + base + 2) = __nv_bfloat162(h[2], h[3]);
    *(__nv_bfloat162*)(g_lo + base)     = __nv_bfloat162(l[0], l[1]);
    *(__nv_bfloat162*)(g_lo + base + 2) = __nv_bfloat162(l[2], l[3]);
}

// ---------------------------------------------------------------------------
// Kernel 2: 4-stage-pipelined mma.sync split-bf16 Gram tile + fused
// histogram + inline finalize by the last CTA (completion ticket).
// 256 threads = 8 warps (2 x 4), warp tile 64x32.
// ---------------------------------------------------------------------------
__global__ __launch_bounds__(256, 2) void ghm_mma_kernel(
        const float* __restrict__ acc_sum, float* __restrict__ out) {
    // triangular decode: tile t -> (by, bx), bx >= by
    int t = blockIdx.x;
    int by = (int)floorf(32.5f - 0.5f * sqrtf(4225.0f - 8.0f * (float)t));
    if (by < 0) by = 0;
    if (by > NT - 1) by = NT - 1;
    int S = by * NT - (by * (by - 1)) / 2;
    while (S + (NT - by) <= t) { S += NT - by; by++; }
    while (S > t) { by--; S -= NT - by; }
    int bx = by + (t - S);
    int rowA = by * TILE, rowB = bx * TILE;

    extern __shared__ __align__(16) char dynsmem[];
    __shared__ int   s_tr[TILE], s_tc[TILE];
    __shared__ float s_cnt[NBINS], s_sum[NBINS];
    __shared__ int   s_last;

    int tid = threadIdx.x, wid = tid >> 5, lid = tid & 31;
    int warp_m = wid & 1;        // 0..1 -> 64-row band
    int warp_n = wid >> 1;       // 0..3 -> 32-col band

    if (tid < NBINS) { s_cnt[tid] = 0.0f; s_sum[tid] = 0.0f; }
    if (tid < TILE) {
        s_tr[tid] = g_tgt[rowA + tid];
        s_tc[tid] = g_tgt[rowB + tid];
    }

    uint32_t sb = smem_to_u32(dynsmem);

    // per-thread cp.async geometry: one 16B chunk per tile per stage
    int p_row = tid >> 1, p_chunk = tid & 1;
    const __nv_bfloat16* srcAh = g_hi + (size_t)(rowA + p_row) * DDIM + p_chunk * 8;
    const __nv_bfloat16* srcAl = g_lo + (size_t)(rowA + p_row) * DDIM + p_chunk * 8;
    const __nv_bfloat16* srcBh = g_hi + (size_t)(rowB + p_row) * DDIM + p_chunk * 8;
    const __nv_bfloat16* srcBl = g_lo + (size_t)(rowB + p_row) * DDIM + p_chunk * 8;
    uint32_t dst_off = (uint32_t)(p_row * SROWB + p_chunk * 16);

    float acc[4][4][4];
    #pragma unroll
    for (int mf = 0; mf < 4; mf++)
        #pragma unroll
        for (int nf = 0; nf < 4; nf++)
            #pragma unroll
            for (int r = 0; r < 4; r++) acc[mf][nf][r] = 0.0f;

    // per-lane ldmatrix address components (bytes, within a stage)
    uint32_t a_off = (uint32_t)((warp_m * 64 + (lid & 15)) * SROWB + (lid >> 4) * 16);
    uint32_t b_off = (uint32_t)((warp_n * 32 + (lid & 7)) * SROWB + ((lid >> 3) & 1) * 16);

    // prologue: fill 3 stages
    #pragma unroll
    for (int s = 0; s < NSTAGE - 1; s++) {
        uint32_t base = sb + s * STAGE_B + dst_off;
        cp16(base,                  srcAh + s * KC);
        cp16(base + TILE_SMEMB,     srcAl + s * KC);
        cp16(base + 2 * TILE_SMEMB, srcBh + s * KC);
        cp16(base + 3 * TILE_SMEMB, srcBl + s * KC);
        CP_COMMIT();
    }

    for (int s = 0; s < NST; s++) {
        CP_WAIT(2);               // stage s arrived (own thread's groups)
        __syncthreads();          // all threads' stage-s data visible

        uint32_t cur = sb + (s & (NSTAGE - 1)) * STAGE_B;
        uint32_t aHi = cur, aLo = cur + TILE_SMEMB;
        uint32_t bHi = cur + 2 * TILE_SMEMB, bLo = cur + 3 * TILE_SMEMB;

        uint32_t bh[4][2], bl[4][2];
        #pragma unroll
        for (int nf = 0; nf < 4; nf++) {
            uint32_t bo = b_off + (uint32_t)(nf * 8 * SROWB);
            ldsm_x2(bh[nf], bHi + bo);
            ldsm_x2(bl[nf], bLo + bo);
        }
        #pragma unroll
        for (int mf = 0; mf < 4; mf++) {
            uint32_t ao = a_off + (uint32_t)(mf * 16 * SROWB);
            uint32_t ah[4], al[4];
            ldsm_x4(ah, aHi + ao);
            ldsm_x4(al, aLo + ao);
            #pragma unroll
            for (int nf = 0; nf < 4; nf++) {
                mma_bf16(acc[mf][nf], ah, bh[nf]);  // hi*hi
                mma_bf16(acc[mf][nf], ah, bl[nf]);  // hi*lo
                mma_bf16(acc[mf][nf], al, bh[nf]);  // lo*hi
            }
        }

        // issue stage s+3 (empty commit keeps group count invariant in tail)
        if (s + NSTAGE - 1 < NST) {
            int sn = s + NSTAGE - 1;
            uint32_t base = sb + (sn & (NSTAGE - 1)) * STAGE_B + dst_off;
            cp16(base,                  srcAh + sn * KC);
            cp16(base + TILE_SMEMB,     srcAl + sn * KC);
            cp16(base + 2 * TILE_SMEMB, srcBh + sn * KC);
            cp16(base + 3 * TILE_SMEMB, srcBl + sn * KC);
        }
        CP_COMMIT();
    }

    // ------------------- epilogue: bin accumulators -------------------
    const float E10 = 1.0f + 1e-6f;           // last edge (fp32, as reference)
    float wf = (bx == by) ? 1.0f : 2.0f;      // off-diag tiles: (i,j) and (j,i)

    float bsum[NBINS], bcnt[NBINS];
    #pragma unroll
    for (int b = 0; b < NBINS; b++) { bsum[b] = 0.0f; bcnt[b] = 0.0f; }

    #pragma unroll
    for (int mf = 0; mf < 4; mf++) {
        int r0 = warp_m * 64 + mf * 16 + (lid >> 2);
        int tr0 = s_tr[r0], tr8 = s_tr[r0 + 8];
        #pragma unroll
        for (int nf = 0; nf < 4; nf++) {
            int c0 = warp_n * 32 + nf * 8 + (lid & 3) * 2;
            int tc0 = s_tc[c0], tc1 = s_tc[c0 + 1];
            int rowt[4] = {tr0, tr0, tr8, tr8};
            int colt[4] = {tc0, tc1, tc0, tc1};
            #pragma unroll
            for (int e = 0; e < 4; e++) {
                float cosv = acc[mf][nf][e];
                float lab  = (rowt[e] == colt[e]) ? 1.0f : 0.0f;
                float dv   = lab - cosv;
                float g    = fabsf(dv);
                // idx in 0..9 valid; 10 (matches no bin) if g >= last edge
                int idx = (g >= 0.1f) + (g >= 0.2f) + (g >= 0.3f) + (g >= 0.4f) +
                          (g >= 0.5f) + (g >= 0.6f) + (g >= 0.7f) + (g >= 0.8f) +
                          (g >= 0.9f) + (g >= E10);
                float g2 = dv * dv;
                #pragma unroll
                for (int b = 0; b < NBINS; b++) {
                    bool hit = (idx == b);
                    bsum[b] += hit ? g2 : 0.0f;
                    bcnt[b] += hit ? 1.0f : 0.0f;
                }
            }
        }
    }

    #pragma unroll
    for (int b = 0; b < NBINS; b++) {
        #pragma unroll
        for (int o = 16; o > 0; o >>= 1) {
            bsum[b] += __shfl_down_sync(0xffffffffu, bsum[b], o);
            bcnt[b] += __shfl_down_sync(0xffffffffu, bcnt[b], o);
        }
    }
    if (lid == 0) {
        #pragma unroll
        for (int b = 0; b < NBINS; b++) {
            atomicAdd(&s_sum[b], wf * bsum[b]);
            atomicAdd(&s_cnt[b], wf * bcnt[b]);
        }
    }
    __syncthreads();
    if (tid < NBINS) {
        atomicAdd(&g_sum[tid], s_sum[tid]);
        atomicAdd(&g_cntf[tid], s_cnt[tid]);
    }

    // ----------------- completion ticket: last CTA finalizes -----------------
    __syncthreads();
    if (tid == 0) {
        __threadfence();
        int done = atomicAdd(&g_ticket, 1);
        s_last = (done == NTRI - 1) ? 1 : 0;
    }
    __syncthreads();
    if (s_last && tid == 0) {
        const float tot = (float)BDIM * (float)BDIM;
        float cts[NBINS], sums[NBINS], vn = 0.0f;
        #pragma unroll
        for (int b = 0; b < NBINS; b++) {
            cts[b]  = atomicAdd(&g_cntf[b], 0.0f);  // L2-coherent read
            sums[b] = atomicAdd(&g_sum[b], 0.0f);
            vn += cts[b];
        }
        float loss = 0.0f;
        #pragma unroll
        for (int b = 0; b < NBINS; b++) {
            float accn = 0.5f * acc_sum[b] + 0.5f * cts[b];  // momentum = 0.5
            float w = tot / (accn + 1e-6f);
            loss += sums[b] * w;
        }
        if (vn > 0.0f) loss /= vn;
        loss /= tot;
        *out = loss;
    }
}

extern "C" void kernel_launch(void* const* d_in, const int* in_sizes, int n_in,
                              void* d_out, int out_size) {
    const float* x       = (const float*)d_in[0];
    const float* acc_sum = (const float*)d_in[1];
    const int*   tgt     = (const int*)d_in[2];   // int32 view; prep sniffs layout
    float*       out     = (float*)d_out;

    cudaFuncSetAttribute(ghm_mma_kernel,
                         cudaFuncAttributeMaxDynamicSharedMemorySize, DYN_SMEM);

    prep_kernel<<<BDIM + 1, 128>>>(x, tgt);
    ghm_mma_kernel<<<NTRI, 256, DYN_SMEM>>>(acc_sum, out);
}

// round 8
// speedup vs baseline: 1.2553x; 1.2553x over previous
#include <cuda_runtime.h>
#include <cuda_fp16.h>
#include <math.h>
#include <stdint.h>

#define BDIM 4096
#define DDIM 512
#define NBINS 10
#define TILE 128
#define NT   32            // tiles per dimension
#define NTRI 528           // NT*(NT+1)/2 upper-triangular tiles
#define KC   32            // fp16 K-elements per pipeline stage (64 B/row)
#define NST  (DDIM / KC)   // 16 stages
#define SROWB 80           // padded SMEM row stride bytes (64B data + 16B pad)
#define TILE_SMEMB (TILE * SROWB)     // 10240 B per tile
#define STAGE_B (3 * TILE_SMEMB)      // A_hi, B_hi, B_lo = 30720 B
#define DYN_SMEM (2 * STAGE_B)        // double buffered = 61440 B

// ---------------------------------------------------------------------------
// device scratch (no allocations allowed)
// ---------------------------------------------------------------------------
__device__ __half g_hi[BDIM * DDIM];
__device__ __half g_lo[BDIM * DDIM];
__device__ int   g_tgt[BDIM];
__device__ float g_cntf[NBINS];
__device__ float g_sum[NBINS];
__device__ int   g_ticket;

// ---------------------------------------------------------------------------
// helpers (base-ISA only: cp.async, ldmatrix, mma.sync — compute_103-safe)
// ---------------------------------------------------------------------------
__device__ __forceinline__ uint32_t smem_to_u32(const void* p) {
    uint32_t a;
    asm("{ .reg .u64 t; cvta.to.shared.u64 t, %1; cvt.u32.u64 %0, t; }"
        : "=r"(a) : "l"(p));
    return a;
}
__device__ __forceinline__ void cp16(uint32_t dst, const void* src) {
    asm volatile("cp.async.cg.shared.global [%0], [%1], 16;" :: "r"(dst), "l"(src));
}
#define CP_COMMIT() asm volatile("cp.async.commit_group;" ::: "memory")
#define CP_WAIT(n)  asm volatile("cp.async.wait_group %0;" :: "n"(n) : "memory")

__device__ __forceinline__ void ldsm_x4(uint32_t* r, uint32_t addr) {
    asm volatile("ldmatrix.sync.aligned.m8n8.x4.shared.b16 {%0,%1,%2,%3}, [%4];"
                 : "=r"(r[0]), "=r"(r[1]), "=r"(r[2]), "=r"(r[3]) : "r"(addr));
}
__device__ __forceinline__ void ldsm_x2(uint32_t* r, uint32_t addr) {
    asm volatile("ldmatrix.sync.aligned.m8n8.x2.shared.b16 {%0,%1}, [%2];"
                 : "=r"(r[0]), "=r"(r[1]) : "r"(addr));
}
__device__ __forceinline__ void mma_f16(float* d, const uint32_t* a, const uint32_t* b) {
    asm volatile("mma.sync.aligned.m16n8k16.row.col.f32.f16.f16.f32 "
                 "{%0,%1,%2,%3}, {%4,%5,%6,%7}, {%8,%9}, {%0,%1,%2,%3};"
                 : "+f"(d[0]), "+f"(d[1]), "+f"(d[2]), "+f"(d[3])
                 : "r"(a[0]), "r"(a[1]), "r"(a[2]), "r"(a[3]),
                   "r"(b[0]), "r"(b[1]));
}

// ---------------------------------------------------------------------------
// Kernel 1: blocks 0..4095 normalize+split rows; block 4096 decodes targets
// (sniffs int32 vs int64 storage) and zeros the histogram/ticket state.
// ---------------------------------------------------------------------------
__global__ void prep_kernel(const float* __restrict__ x,
                            const int* __restrict__ tgt_words) {
    int blk = blockIdx.x;
    int tid = threadIdx.x;  // 0..127

    if (blk == BDIM) {
        __shared__ int s_any_odd;
        if (tid == 0) s_any_odd = 0;
        __syncthreads();
        int local = 0;
        #pragma unroll
        for (int r = 0; r < 32; r++) {
            int i = tid + r * 128;
            local |= tgt_words[2 * i + 1];   // odd word under int64 hypothesis
        }
        if (local) atomicOr(&s_any_odd, 1);
        __syncthreads();
        bool is32 = (s_any_odd != 0);
        #pragma unroll
        for (int r = 0; r < 32; r++) {
            int i = tid + r * 128;
            g_tgt[i] = is32 ? tgt_words[i] : tgt_words[2 * i];
        }
        if (tid < NBINS) { g_cntf[tid] = 0.0f; g_sum[tid] = 0.0f; }
        if (tid == 0) g_ticket = 0;
        return;
    }

    float4 v = ((const float4*)(x + (size_t)blk * DDIM))[tid];
    float ss = v.x * v.x + v.y * v.y + v.z * v.z + v.w * v.w;
    #pragma unroll
    for (int o = 16; o > 0; o >>= 1) ss += __shfl_down_sync(0xffffffffu, ss, o);
    __shared__ float ws[4];
    if ((tid & 31) == 0) ws[tid >> 5] = ss;
    __syncthreads();
    float tot = ws[0] + ws[1] + ws[2] + ws[3];
    float inv = 1.0f / fmaxf(sqrtf(tot), 1e-12f);

    float f[4] = {v.x * inv, v.y * inv, v.z * inv, v.w * inv};
    __half h[4], l[4];
    #pragma unroll
    for (int i = 0; i < 4; i++) {
        h[i] = __float2half(f[i]);
        l[i] = __float2half(f[i] - __half2float(h[i]));
    }
    size_t base = (size_t)blk * DDIM + tid * 4;
    *(__half2*)(g_hi + base)     = __half2(h[0], h[1]);
    *(__half2*)(g_hi + base + 2) = __half2(h[2], h[3]);
    *(__half2*)(g_lo + base)     = __half2(l[0], l[1]);
    *(__half2*)(g_lo + base + 2) = __half2(l[2], l[3]);
}

// ---------------------------------------------------------------------------
// stage loader: 3 tiles (A_hi, B_hi, B_lo), 128 rows x 32 fp16 (64 B),
// rows padded to 80 B. 6 cp.async.128 per thread.
// ---------------------------------------------------------------------------
__device__ __forceinline__ void issue_stage(uint32_t sbase, int kb,
                                            int rowA, int rowB, int tid) {
    #pragma unroll
    for (int rr = 0; rr < 2; rr++) {
        int idx = rr * 256 + tid;
        int r = idx >> 2, c = idx & 3;
        uint32_t d = sbase + r * SROWB + c * 16;
        size_t go = (size_t)r * DDIM + kb * KC + c * 8;
        cp16(d,                  g_hi + (size_t)rowA * DDIM + go);
        cp16(d + TILE_SMEMB,     g_hi + (size_t)rowB * DDIM + go);
        cp16(d + 2 * TILE_SMEMB, g_lo + (size_t)rowB * DDIM + go);
    }
}

// ---------------------------------------------------------------------------
// Kernel 2: pipelined 2-term fp16-split Gram tile + fused histogram +
// inline finalize by the last CTA. 256 threads = 8 warps (2x4), warp 64x32.
// cos ~= hi_i*hi_j + hi_i*lo_j   (dropped lo_i*x_j term ~2e-5)
// ---------------------------------------------------------------------------
__global__ __launch_bounds__(256, 2) void ghm_mma_kernel(
        const float* __restrict__ acc_sum, float* __restrict__ out) {
    // triangular decode: tile t -> (by, bx), bx >= by
    int t = blockIdx.x;
    int by = (int)floorf(32.5f - 0.5f * sqrtf(4225.0f - 8.0f * (float)t));
    if (by < 0) by = 0;
    if (by > NT - 1) by = NT - 1;
    int S = by * NT - (by * (by - 1)) / 2;
    while (S + (NT - by) <= t) { S += NT - by; by++; }
    while (S > t) { by--; S -= NT - by; }
    int bx = by + (t - S);
    int rowA = by * TILE, rowB = bx * TILE;

    extern __shared__ __align__(16) char dynsmem[];
    __shared__ int   s_tr[TILE], s_tc[TILE];
    __shared__ float s_cnt[NBINS], s_sum[NBINS];
    __shared__ int   s_last;

    int tid = threadIdx.x, wid = tid >> 5, lid = tid & 31;
    int warp_m = wid & 1;        // 0..1 -> 64-row band
    int warp_n = wid >> 1;       // 0..3 -> 32-col band

    if (tid < NBINS) { s_cnt[tid] = 0.0f; s_sum[tid] = 0.0f; }
    if (tid < TILE) {
        s_tr[tid] = g_tgt[rowA + tid];
        s_tc[tid] = g_tgt[rowB + tid];
    }

    uint32_t sb0 = smem_to_u32(dynsmem);
    uint32_t sb1 = sb0 + STAGE_B;

    float acc[4][4][4];
    #pragma unroll
    for (int mf = 0; mf < 4; mf++)
        #pragma unroll
        for (int nf = 0; nf < 4; nf++)
            #pragma unroll
            for (int r = 0; r < 4; r++) acc[mf][nf][r] = 0.0f;

    // per-lane ldmatrix address components (bytes, within a stage)
    uint32_t a_off = (uint32_t)((warp_m * 64 + (lid & 15)) * SROWB + (lid >> 4) * 16);
    uint32_t b_off = (uint32_t)((warp_n * 32 + (lid & 7)) * SROWB + ((lid >> 3) & 1) * 16);

    issue_stage(sb0, 0, rowA, rowB, tid);
    CP_COMMIT();

    for (int kb = 0; kb < NST; kb++) {
        uint32_t cur = (kb & 1) ? sb1 : sb0;
        if (kb + 1 < NST) {
            issue_stage((kb & 1) ? sb0 : sb1, kb + 1, rowA, rowB, tid);
            CP_COMMIT();
            CP_WAIT(1);
        } else {
            CP_WAIT(0);
        }
        __syncthreads();

        uint32_t aHi = cur;
        uint32_t bHi = cur + TILE_SMEMB, bLo = cur + 2 * TILE_SMEMB;

        #pragma unroll
        for (int ks = 0; ks < 2; ks++) {
            uint32_t kcol = (uint32_t)(ks * 32);
            uint32_t bh[4][2], bl[4][2];
            #pragma unroll
            for (int nf = 0; nf < 4; nf++) {
                uint32_t bo = b_off + (uint32_t)(nf * 8 * SROWB) + kcol;
                ldsm_x2(bh[nf], bHi + bo);
                ldsm_x2(bl[nf], bLo + bo);
            }
            #pragma unroll
            for (int mf = 0; mf < 4; mf++) {
                uint32_t ao = a_off + (uint32_t)(mf * 16 * SROWB) + kcol;
                uint32_t ah[4];
                ldsm_x4(ah, aHi + ao);
                // two passes: dependent MMA pairs are 4 apart -> ILP
                #pragma unroll
                for (int nf = 0; nf < 4; nf++)
                    mma_f16(acc[mf][nf], ah, bh[nf]);  // hi*hi
                #pragma unroll
                for (int nf = 0; nf < 4; nf++)
                    mma_f16(acc[mf][nf], ah, bl[nf]);  // hi*lo
            }
        }
        __syncthreads();
    }

    // ------------------- epilogue: bin accumulators -------------------
    const float E10 = 1.0f + 1e-6f;           // last edge (fp32, as reference)
    float wf = (bx == by) ? 1.0f : 2.0f;      // off-diag tiles: (i,j) and (j,i)

    float bsum[NBINS], bcnt[NBINS];
    #pragma unroll
    for (int b = 0; b < NBINS; b++) { bsum[b] = 0.0f; bcnt[b] = 0.0f; }

    #pragma unroll
    for (int mf = 0; mf < 4; mf++) {
        int r0 = warp_m * 64 + mf * 16 + (lid >> 2);
        int tr0 = s_tr[r0], tr8 = s_tr[r0 + 8];
        #pragma unroll
        for (int nf = 0; nf < 4; nf++) {
            int c0 = warp_n * 32 + nf * 8 + (lid & 3) * 2;
            int tc0 = s_tc[c0], tc1 = s_tc[c0 + 1];
            int rowt[4] = {tr0, tr0, tr8, tr8};
            int colt[4] = {tc0, tc1, tc0, tc1};
            #pragma unroll
            for (int e = 0; e < 4; e++) {
                float cosv = acc[mf][nf][e];
                float lab  = (rowt[e] == colt[e]) ? 1.0f : 0.0f;
                float dv   = lab - cosv;
                float g    = fabsf(dv);
                // idx in 0..9 valid; 10 (matches no bin) if g >= last edge
                int idx = (g >= 0.1f) + (g >= 0.2f) + (g >= 0.3f) + (g >= 0.4f) +
                          (g >= 0.5f) + (g >= 0.6f) + (g >= 0.7f) + (g >= 0.8f) +
                          (g >= 0.9f) + (g >= E10);
                float g2 = dv * dv;
                #pragma unroll
                for (int b = 0; b < NBINS; b++) {
                    bool hit = (idx == b);
                    bsum[b] += hit ? g2 : 0.0f;
                    bcnt[b] += hit ? 1.0f : 0.0f;
                }
            }
        }
    }

    #pragma unroll
    for (int b = 0; b < NBINS; b++) {
        #pragma unroll
        for (int o = 16; o > 0; o >>= 1) {
            bsum[b] += __shfl_down_sync(0xffffffffu, bsum[b], o);
            bcnt[b] += __shfl_down_sync(0xffffffffu, bcnt[b], o);
        }
    }
    if (lid == 0) {
        #pragma unroll
        for (int b = 0; b < NBINS; b++) {
            atomicAdd(&s_sum[b], wf * bsum[b]);
            atomicAdd(&s_cnt[b], wf * bcnt[b]);
        }
    }
    __syncthreads();
    if (tid < NBINS) {
        atomicAdd(&g_sum[tid], s_sum[tid]);
        atomicAdd(&g_cntf[tid], s_cnt[tid]);
    }

    // ----------------- completion ticket: last CTA finalizes -----------------
    __syncthreads();
    if (tid == 0) {
        __threadfence();
        int done = atomicAdd(&g_ticket, 1);
        s_last = (done == NTRI - 1) ? 1 : 0;
    }
    __syncthreads();
    if (s_last && tid == 0) {
        const float tot = (float)BDIM * (float)BDIM;
        float cts[NBINS], sums[NBINS], vn = 0.0f;
        #pragma unroll
        for (int b = 0; b < NBINS; b++) {
            cts[b]  = atomicAdd(&g_cntf[b], 0.0f);  // L2-coherent read
            sums[b] = atomicAdd(&g_sum[b], 0.0f);
            vn += cts[b];
        }
        float loss = 0.0f;
        #pragma unroll
        for (int b = 0; b < NBINS; b++) {
            float accn = 0.5f * acc_sum[b] + 0.5f * cts[b];  // momentum = 0.5
            float w = tot / (accn + 1e-6f);
            loss += sums[b] * w;
        }
        if (vn > 0.0f) loss /= vn;
        loss /= tot;
        *out = loss;
    }
}

extern "C" void kernel_launch(void* const* d_in, const int* in_sizes, int n_in,
                              void* d_out, int out_size) {
    const float* x       = (const float*)d_in[0];
    const float* acc_sum = (const float*)d_in[1];
    const int*   tgt     = (const int*)d_in[2];   // int32 view; prep sniffs layout
    float*       out     = (float*)d_out;

    cudaFuncSetAttribute(ghm_mma_kernel,
                         cudaFuncAttributeMaxDynamicSharedMemorySize, DYN_SMEM);

    prep_kernel<<<BDIM + 1, 128>>>(x, tgt);
    ghm_mma_kernel<<<NTRI, 256, DYN_SMEM>>>(acc_sum, out);
}

// round 9
// speedup vs baseline: 1.6115x; 1.2838x over previous
#include <cuda_runtime.h>
#include <cuda_fp16.h>
#include <math.h>
#include <stdint.h>

#define BDIM 4096
#define DDIM 512
#define NBINS 10
#define TILE 128
#define NT   32            // tiles per dimension
#define NTRI 528           // NT*(NT+1)/2 upper-triangular tiles
#define KC   32            // fp16 K-elements per pipeline stage (64 B/row)
#define NST  (DDIM / KC)   // 16 stages
#define SROWB 80           // padded SMEM row stride bytes (64B data + 16B pad)
#define TILE_SMEMB (TILE * SROWB)     // 10240 B per tile
#define STAGE_B (3 * TILE_SMEMB)      // A_hi, B_hi, B_lo = 30720 B
#define NSTAGE 3
#define DYN_SMEM (NSTAGE * STAGE_B)   // 92160 B

// ---------------------------------------------------------------------------
// device scratch (no allocations allowed)
// ---------------------------------------------------------------------------
__device__ __half g_hi[BDIM * DDIM];
__device__ __half g_lo[BDIM * DDIM];
__device__ int   g_tgt[BDIM];
__device__ float g_cntf[NBINS];
__device__ float g_sum[NBINS];
__device__ int   g_ticket;

// ---------------------------------------------------------------------------
// helpers (base-ISA only: cp.async, ldmatrix, mma.sync — compute_103-safe)
// ---------------------------------------------------------------------------
__device__ __forceinline__ uint32_t smem_to_u32(const void* p) {
    uint32_t a;
    asm("{ .reg .u64 t; cvta.to.shared.u64 t, %1; cvt.u32.u64 %0, t; }"
        : "=r"(a) : "l"(p));
    return a;
}
__device__ __forceinline__ void cp16(uint32_t dst, const void* src) {
    asm volatile("cp.async.cg.shared.global [%0], [%1], 16;" :: "r"(dst), "l"(src));
}
#define CP_COMMIT() asm volatile("cp.async.commit_group;" ::: "memory")
#define CP_WAIT(n)  asm volatile("cp.async.wait_group %0;" :: "n"(n) : "memory")

__device__ __forceinline__ void ldsm_x4(uint32_t* r, uint32_t addr) {
    asm volatile("ldmatrix.sync.aligned.m8n8.x4.shared.b16 {%0,%1,%2,%3}, [%4];"
                 : "=r"(r[0]), "=r"(r[1]), "=r"(r[2]), "=r"(r[3]) : "r"(addr));
}
__device__ __forceinline__ void mma_f16(float* d, const uint32_t* a, const uint32_t* b) {
    asm volatile("mma.sync.aligned.m16n8k16.row.col.f32.f16.f16.f32 "
                 "{%0,%1,%2,%3}, {%4,%5,%6,%7}, {%8,%9}, {%0,%1,%2,%3};"
                 : "+f"(d[0]), "+f"(d[1]), "+f"(d[2]), "+f"(d[3])
                 : "r"(a[0]), "r"(a[1]), "r"(a[2]), "r"(a[3]),
                   "r"(b[0]), "r"(b[1]));
}

// ---------------------------------------------------------------------------
// Kernel 1: blocks 0..4095 normalize+split rows; block 4096 decodes targets
// (sniffs int32 vs int64 storage) and zeros the histogram/ticket state.
// ---------------------------------------------------------------------------
__global__ void prep_kernel(const float* __restrict__ x,
                            const int* __restrict__ tgt_words) {
    int blk = blockIdx.x;
    int tid = threadIdx.x;  // 0..127

    if (blk == BDIM) {
        __shared__ int s_any_odd;
        if (tid == 0) s_any_odd = 0;
        __syncthreads();
        int local = 0;
        #pragma unroll
        for (int r = 0; r < 32; r++) {
            int i = tid + r * 128;
            local |= tgt_words[2 * i + 1];   // odd word under int64 hypothesis
        }
        if (local) atomicOr(&s_any_odd, 1);
        __syncthreads();
        bool is32 = (s_any_odd != 0);
        #pragma unroll
        for (int r = 0; r < 32; r++) {
            int i = tid + r * 128;
            g_tgt[i] = is32 ? tgt_words[i] : tgt_words[2 * i];
        }
        if (tid < NBINS) { g_cntf[tid] = 0.0f; g_sum[tid] = 0.0f; }
        if (tid == 0) g_ticket = 0;
        return;
    }

    float4 v = ((const float4*)(x + (size_t)blk * DDIM))[tid];
    float ss = v.x * v.x + v.y * v.y + v.z * v.z + v.w * v.w;
    #pragma unroll
    for (int o = 16; o > 0; o >>= 1) ss += __shfl_down_sync(0xffffffffu, ss, o);
    __shared__ float ws[4];
    if ((tid & 31) == 0) ws[tid >> 5] = ss;
    __syncthreads();
    float tot = ws[0] + ws[1] + ws[2] + ws[3];
    float inv = 1.0f / fmaxf(sqrtf(tot), 1e-12f);

    float f[4] = {v.x * inv, v.y * inv, v.z * inv, v.w * inv};
    __half h[4], l[4];
    #pragma unroll
    for (int i = 0; i < 4; i++) {
        h[i] = __float2half(f[i]);
        l[i] = __float2half(f[i] - __half2float(h[i]));
    }
    size_t base = (size_t)blk * DDIM + tid * 4;
    *(__half2*)(g_hi + base)     = __half2(h[0], h[1]);
    *(__half2*)(g_hi + base + 2) = __half2(h[2], h[3]);
    *(__half2*)(g_lo + base)     = __half2(l[0], l[1]);
    *(__half2*)(g_lo + base + 2) = __half2(l[2], l[3]);
}

// ---------------------------------------------------------------------------
// Kernel 2: 3-stage ring pipelined 2-term fp16-split Gram tile + fused
// histogram + inline finalize by last CTA. 256 threads = 8 warps (2x4),
// warp tile 64x32.  cos ~= hi_i*hi_j + hi_i*lo_j
// ---------------------------------------------------------------------------
__global__ __launch_bounds__(256, 2) void ghm_mma_kernel(
        const float* __restrict__ acc_sum, float* __restrict__ out) {
    // triangular decode: tile t -> (by, bx), bx >= by
    int t = blockIdx.x;
    int by = (int)floorf(32.5f - 0.5f * sqrtf(4225.0f - 8.0f * (float)t));
    if (by < 0) by = 0;
    if (by > NT - 1) by = NT - 1;
    int S = by * NT - (by * (by - 1)) / 2;
    while (S + (NT - by) <= t) { S += NT - by; by++; }
    while (S > t) { by--; S -= NT - by; }
    int bx = by + (t - S);
    int rowA = by * TILE, rowB = bx * TILE;

    extern __shared__ __align__(16) char dynsmem[];
    __shared__ int   s_tr[TILE], s_tc[TILE];
    __shared__ float s_cnt[NBINS], s_sum[NBINS];
    __shared__ int   s_last;

    int tid = threadIdx.x, wid = tid >> 5, lid = tid & 31;
    int warp_m = wid & 1;        // 0..1 -> 64-row band
    int warp_n = wid >> 1;       // 0..3 -> 32-col band

    if (tid < NBINS) { s_cnt[tid] = 0.0f; s_sum[tid] = 0.0f; }
    if (tid < TILE) {
        s_tr[tid] = g_tgt[rowA + tid];
        s_tc[tid] = g_tgt[rowB + tid];
    }

    uint32_t sb = smem_to_u32(dynsmem);
    uint32_t sbase[NSTAGE] = {sb, sb + STAGE_B, sb + 2 * STAGE_B};

    // per-thread cp.async geometry: two 16B chunks per tile per stage
    int r0 = tid >> 2, c0 = tid & 3;                 // chunk 0: rows 0..63
    int roff0 = r0 * DDIM + c0 * 8;                  // element offsets (fp16)
    int roff1 = (r0 + 64) * DDIM + c0 * 8;           // chunk 1: rows 64..127
    uint32_t doff0 = (uint32_t)(r0 * SROWB + c0 * 16);
    uint32_t doff1 = (uint32_t)((r0 + 64) * SROWB + c0 * 16);

    // mutable source pointers, advanced KC elements per issued stage
    const __half* pA  = g_hi + (size_t)rowA * DDIM;
    const __half* pBh = g_hi + (size_t)rowB * DDIM;
    const __half* pBl = g_lo + (size_t)rowB * DDIM;

    float acc[4][4][4];
    #pragma unroll
    for (int mf = 0; mf < 4; mf++)
        #pragma unroll
        for (int nf = 0; nf < 4; nf++)
            #pragma unroll
            for (int r = 0; r < 4; r++) acc[mf][nf][r] = 0.0f;

    // ldmatrix lane addressing (within a stage):
    // A x4: rows (lid&15), k-chunk (lid>>4)
    uint32_t a_off = (uint32_t)((warp_m * 64 + (lid & 15)) * SROWB + (lid >> 4) * 16);
    // B x4 fused hi+lo: groups 0,1 -> B_hi chunks 0,1; groups 2,3 -> B_lo (+TILE_SMEMB)
    uint32_t b_off = (uint32_t)(TILE_SMEMB +                        // B_hi tile base
                     (warp_n * 32 + (lid & 7)) * SROWB +
                     ((lid >> 3) & 1) * 16 +
                     (lid >> 4) * TILE_SMEMB);                      // lanes 16-31 -> B_lo

    // prologue: issue stages 0, 1
    #pragma unroll
    for (int s = 0; s < 2; s++) {
        uint32_t base = sbase[s];
        cp16(base + doff0,                  pA  + roff0);
        cp16(base + doff1,                  pA  + roff1);
        cp16(base + TILE_SMEMB + doff0,     pBh + roff0);
        cp16(base + TILE_SMEMB + doff1,     pBh + roff1);
        cp16(base + 2 * TILE_SMEMB + doff0, pBl + roff0);
        cp16(base + 2 * TILE_SMEMB + doff1, pBl + roff1);
        CP_COMMIT();
        pA += KC; pBh += KC; pBl += KC;
    }

    int cb = 0;      // compute buffer (kb % 3)
    int ib = 2;      // issue buffer  ((kb+2) % 3)
    for (int kb = 0; kb < NST; kb++) {
        CP_WAIT(1);          // own stage-kb group complete
        __syncthreads();     // all warps done reading buffer ib (stage kb-1)

        if (kb + 2 < NST) {  // issue stage kb+2 into buffer ib
            uint32_t base = sbase[ib];
            cp16(base + doff0,                  pA  + roff0);
            cp16(base + doff1,                  pA  + roff1);
            cp16(base + TILE_SMEMB + doff0,     pBh + roff0);
            cp16(base + TILE_SMEMB + doff1,     pBh + roff1);
            cp16(base + 2 * TILE_SMEMB + doff0, pBl + roff0);
            cp16(base + 2 * TILE_SMEMB + doff1, pBl + roff1);
            pA += KC; pBh += KC; pBl += KC;
        }
        CP_COMMIT();         // always (empty group keeps accounting exact)

        uint32_t cur = sbase[cb];
        #pragma unroll
        for (int ks = 0; ks < 2; ks++) {
            uint32_t kcol = (uint32_t)(ks * 32);
            uint32_t bf4[4][4];
            #pragma unroll
            for (int nf = 0; nf < 4; nf++)
                ldsm_x4(bf4[nf], cur + b_off + (uint32_t)(nf * 8 * SROWB) + kcol);
            #pragma unroll
            for (int mf = 0; mf < 4; mf++) {
                uint32_t ah[4];
                ldsm_x4(ah, cur + a_off + (uint32_t)(mf * 16 * SROWB) + kcol);
                #pragma unroll
                for (int nf = 0; nf < 4; nf++)
                    mma_f16(acc[mf][nf], ah, &bf4[nf][0]);  // hi*hi
                #pragma unroll
                for (int nf = 0; nf < 4; nf++)
                    mma_f16(acc[mf][nf], ah, &bf4[nf][2]);  // hi*lo
            }
        }
        cb = (cb == 2) ? 0 : cb + 1;
        ib = (ib == 2) ? 0 : ib + 1;
    }

    // ------------------- epilogue: bin accumulators -------------------
    const float E10 = 1.0f + 1e-6f;           // last edge (fp32, as reference)
    float wf = (bx == by) ? 1.0f : 2.0f;      // off-diag tiles: (i,j) and (j,i)

    float bsum[NBINS], bcnt[NBINS];
    #pragma unroll
    for (int b = 0; b < NBINS; b++) { bsum[b] = 0.0f; bcnt[b] = 0.0f; }

    #pragma unroll
    for (int mf = 0; mf < 4; mf++) {
        int rr = warp_m * 64 + mf * 16 + (lid >> 2);
        int tr0 = s_tr[rr], tr8 = s_tr[rr + 8];
        #pragma unroll
        for (int nf = 0; nf < 4; nf++) {
            int cc = warp_n * 32 + nf * 8 + (lid & 3) * 2;
            int tc0 = s_tc[cc], tc1 = s_tc[cc + 1];
            int rowt[4] = {tr0, tr0, tr8, tr8};
            int colt[4] = {tc0, tc1, tc0, tc1};
            #pragma unroll
            for (int e = 0; e < 4; e++) {
                float cosv = acc[mf][nf][e];
                float lab  = (rowt[e] == colt[e]) ? 1.0f : 0.0f;
                float dv   = lab - cosv;
                float g    = fabsf(dv);
                int idx = (int)(g * 10.0f);            // fast binning
                idx = (idx > 9) ? ((g < E10) ? 9 : 10) : idx;  // [1.0,1+1e-6)->bin9
                float g2 = dv * dv;
                #pragma unroll
                for (int b = 0; b < NBINS; b++) {
                    bool hit = (idx == b);
                    bsum[b] += hit ? g2 : 0.0f;
                    bcnt[b] += hit ? 1.0f : 0.0f;
                }
            }
        }
    }

    #pragma unroll
    for (int b = 0; b < NBINS; b++) {
        #pragma unroll
        for (int o = 16; o > 0; o >>= 1) {
            bsum[b] += __shfl_down_sync(0xffffffffu, bsum[b], o);
            bcnt[b] += __shfl_down_sync(0xffffffffu, bcnt[b], o);
        }
    }
    if (lid == 0) {
        #pragma unroll
        for (int b = 0; b < NBINS; b++) {
            atomicAdd(&s_sum[b], wf * bsum[b]);
            atomicAdd(&s_cnt[b], wf * bcnt[b]);
        }
    }
    __syncthreads();
    if (tid < NBINS) {
        atomicAdd(&g_sum[tid], s_sum[tid]);
        atomicAdd(&g_cntf[tid], s_cnt[tid]);
    }

    // ----------------- completion ticket: last CTA finalizes -----------------
    __syncthreads();
    if (tid == 0) {
        __threadfence();
        int done = atomicAdd(&g_ticket, 1);
        s_last = (done == NTRI - 1) ? 1 : 0;
    }
    __syncthreads();
    if (s_last && tid == 0) {
        const float tot = (float)BDIM * (float)BDIM;
        float cts[NBINS], sums[NBINS], vn = 0.0f;
        #pragma unroll
        for (int b = 0; b < NBINS; b++) {
            cts[b]  = atomicAdd(&g_cntf[b], 0.0f);  // L2-coherent read
            sums[b] = atomicAdd(&g_sum[b], 0.0f);
            vn += cts[b];
        }
        float loss = 0.0f;
        #pragma unroll
        for (int b = 0; b < NBINS; b++) {
            float accn = 0.5f * acc_sum[b] + 0.5f * cts[b];  // momentum = 0.5
            float w = tot / (accn + 1e-6f);
            loss += sums[b] * w;
        }
        if (vn > 0.0f) loss /= vn;
        loss /= tot;
        *out = loss;
    }
}

extern "C" void kernel_launch(void* const* d_in, const int* in_sizes, int n_in,
                              void* d_out, int out_size) {
    const float* x       = (const float*)d_in[0];
    const float* acc_sum = (const float*)d_in[1];
    const int*   tgt     = (const int*)d_in[2];   // int32 view; prep sniffs layout
    float*       out     = (float*)d_out;

    cudaFuncSetAttribute(ghm_mma_kernel,
                         cudaFuncAttributeMaxDynamicSharedMemorySize, DYN_SMEM);

    prep_kernel<<<BDIM + 1, 128>>>(x, tgt);
    ghm_mma_kernel<<<NTRI, 256, DYN_SMEM>>>(acc_sum, out);
}